// round 13
// baseline (speedup 1.0000x reference)
#include <cuda_runtime.h>
#include <cuda_bf16.h>
#include <math.h>

// Problem constants
#define BB 2
#define NN 8192
#define EN 16
#define CC 256
#define FF 512
#define HEADS 8
#define DE 8
#define DD 32            // C / HEADS
#define BN_TOT (BB * NN) // 16384
#define MS (BN_TOT * DE) // 131072
#define C3 259           // C + 3
#define KS_PAD 272       // 259 padded up to multiple of 16
#define SF_LD 260        // sf row stride (16B-aligned)

typedef unsigned long long u64;

// ---------------------------------------------------------------------------
// Packed f32x2 FMA helpers (sm_103a; FFMA2 only reachable via PTX)
// ---------------------------------------------------------------------------
__device__ __forceinline__ u64 pack_dup(float x) {
    u64 r;
    asm("mov.b64 %0, {%1, %1};" : "=l"(r) : "f"(x));
    return r;
}
__device__ __forceinline__ void ffma2(u64& d, u64 a, u64 b) {
    asm("fma.rn.f32x2 %0, %1, %2, %0;" : "+l"(d) : "l"(a), "l"(b));
}
__device__ __forceinline__ float2 unpack2(u64 v) {
    float2 r;
    asm("mov.b64 {%0, %1}, %2;" : "=f"(r.x), "=f"(r.y) : "l"(v));
    return r;
}

// ---------------------------------------------------------------------------
// Scratch (device globals; no allocation allowed)
// ---------------------------------------------------------------------------
__device__ float g_featsT[BN_TOT * CC]; // features transposed (B,N,C)
__device__ float g_x[BN_TOT * CC];      // LN output
__device__ float g_q[BN_TOT * CC];      // Q
__device__ float g_H[BN_TOT * 128];     // relu(x@D1+db1) per source node
__device__ float g_L[BN_TOT * DE];      // edge-MLP logits per source node
__device__ float g_r[MS * KS_PAD];      // r[n,h,c] = Wk_h @ q_h  (n*8+h, c)
__device__ float g_agg[(size_t)HEADS * BN_TOT * KS_PAD]; // per-head sm-weighted s
__device__ float g_ao[BN_TOT * CC];     // attention output (pre-Wo)
__device__ float g_f1[BN_TOT * CC];     // feats + o
__device__ float g_mid[BN_TOT * FF];    // FFN hidden
__device__ float g_f2[BN_TOT * CC];     // final feats (B,N,C)

// ---------------------------------------------------------------------------
// Transpose (B, R, S) -> (B, S, R). grid: (S/32, R/32, B), block: (32, 8)
// ---------------------------------------------------------------------------
__global__ void transpose_kernel(const float* __restrict__ in,
                                 float* __restrict__ out, int R, int S) {
    __shared__ float tile[32][33];
    int b = blockIdx.z;
    int s0 = blockIdx.x * 32;
    int r0 = blockIdx.y * 32;
    int tx = threadIdx.x, ty = threadIdx.y;
#pragma unroll
    for (int i = 0; i < 4; i++) {
        tile[ty + i * 8][tx] =
            in[((size_t)b * R + (r0 + ty + i * 8)) * S + s0 + tx];
    }
    __syncthreads();
#pragma unroll
    for (int i = 0; i < 4; i++) {
        out[((size_t)b * S + (s0 + ty + i * 8)) * R + r0 + tx] =
            tile[tx][ty + i * 8];
    }
}

// ---------------------------------------------------------------------------
// LayerNorm over last dim (=256). grid: rows, block: 256
// ---------------------------------------------------------------------------
__global__ void ln_kernel(const float* __restrict__ in, float* __restrict__ out,
                          const float* __restrict__ g, const float* __restrict__ be) {
    int row = blockIdx.x;
    int t = threadIdx.x;
    __shared__ float red[8];
    __shared__ float mv[2];
    float v = in[(size_t)row * CC + t];

    float s = v;
#pragma unroll
    for (int off = 16; off > 0; off >>= 1) s += __shfl_xor_sync(0xffffffffu, s, off);
    if ((t & 31) == 0) red[t >> 5] = s;
    __syncthreads();
    if (t == 0) {
        float tot = 0.f;
#pragma unroll
        for (int i = 0; i < 8; i++) tot += red[i];
        mv[0] = tot * (1.0f / CC);
    }
    __syncthreads();
    float mean = mv[0];
    float d = v - mean;
    s = d * d;
#pragma unroll
    for (int off = 16; off > 0; off >>= 1) s += __shfl_xor_sync(0xffffffffu, s, off);
    if ((t & 31) == 0) red[t >> 5] = s;
    __syncthreads();
    if (t == 0) {
        float tot = 0.f;
#pragma unroll
        for (int i = 0; i < 8; i++) tot += red[i];
        mv[1] = tot * (1.0f / CC);
    }
    __syncthreads();
    float var = mv[1];
    out[(size_t)row * CC + t] = d * rsqrtf(var + 1e-6f) * g[t] + be[t];
}

// ---------------------------------------------------------------------------
// L-projection: L[j, de] = H[j, :] @ D2[:, de] + db2[de]
// grid: BN/32, block 256 = (32 rows x 8 de)
// ---------------------------------------------------------------------------
__global__ __launch_bounds__(256) void lproj_kernel(
    const float* __restrict__ H, const float* __restrict__ D2,
    const float* __restrict__ db2, float* __restrict__ L) {
    __shared__ __align__(16) float Hs[32][128];
    __shared__ float D2s[128][8];
    int t = threadIdx.x;
    int m0 = blockIdx.x * 32;

    // load 32 H rows (32x128 = 4096 floats; 4 float4 per thread)
#pragma unroll
    for (int i = 0; i < 4; i++) {
        int lin = i * 256 + t;        // 0..1023 float4
        int r = lin >> 5, c4 = (lin & 31) * 4;
        *(float4*)&Hs[r][c4] =
            *(const float4*)&H[(size_t)(m0 + r) * 128 + c4];
    }
#pragma unroll
    for (int i = 0; i < 4; i++) {
        int lin = i * 256 + t;
        D2s[lin >> 3][lin & 7] = D2[lin];
    }
    __syncthreads();

    int r = t >> 3, de = t & 7;
    float s = db2[de];
#pragma unroll 8
    for (int k = 0; k < 128; k++) s = fmaf(Hs[r][k], D2s[k][de], s);
    L[(size_t)(m0 + r) * DE + de] = s;
}

// ---------------------------------------------------------------------------
// r-projection: R[n, h, c] = sum_d q[n, h*32+d] * Wk[c, h*32+d]
// grid: (272/16 = 17 c-tiles, BN/16 n-tiles), block: 256 (16n x 16c)
// Rows c >= 259 produce zeros (pad).
// ---------------------------------------------------------------------------
__global__ __launch_bounds__(256) void rproj_kernel(
    const float* __restrict__ q, const float* __restrict__ Wk,
    float* __restrict__ R) {
    __shared__ __align__(16) float qs[16][CC];
    __shared__ __align__(16) float wks[16][260];
    int t = threadIdx.x;
    int c0 = blockIdx.x * 16;
    int n0 = blockIdx.y * 16;

    for (int i = t; i < 16 * CC; i += 256) {
        int r = i >> 8, cc = i & 255;
        qs[r][cc] = q[(size_t)(n0 + r) * CC + cc];
        int crow = c0 + r;
        wks[r][cc] = (crow < C3) ? Wk[(size_t)crow * CC + cc] : 0.f;
    }
    __syncthreads();

    int ni = t >> 4, ci = t & 15;
#pragma unroll
    for (int h = 0; h < HEADS; h++) {
        float a = 0.f;
#pragma unroll
        for (int d = 0; d < DD; d += 4) {
            float4 qv = *(const float4*)&qs[ni][h * DD + d];
            float4 wv = *(const float4*)&wks[ci][h * DD + d];
            a = fmaf(qv.x, wv.x, a);
            a = fmaf(qv.y, wv.y, a);
            a = fmaf(qv.z, wv.z, a);
            a = fmaf(qv.w, wv.w, a);
        }
        R[((size_t)(n0 + ni) * DE + h) * KS_PAD + c0 + ci] = a;
    }
}

// ---------------------------------------------------------------------------
// Per-node kernel: gather sf/L/coords -> gumbel softmax -> aggregate s ->
// simi (via r) -> attn softmax -> per-head aggregation.
// grid: B*N, block: 256
// ---------------------------------------------------------------------------
__global__ __launch_bounds__(256) void node_kernel(
    const float* __restrict__ xyz, const int* __restrict__ edges,
    const float* __restrict__ gu, const float* __restrict__ Lg,
    const float* __restrict__ xin, const float* __restrict__ R,
    float* __restrict__ aggP) {
    int m = blockIdx.x;
    int b = m >> 13;
    int n = m & (NN - 1);
    int t = threadIdx.x;

    __shared__ __align__(16) float sf[EN][SF_LD];
    __shared__ float scs[EN][3];
    __shared__ int sidx[EN];
    __shared__ float lg[DE][EN];
    __shared__ float wsh[DE][EN];
    __shared__ __align__(16) float rs[DE][KS_PAD];
    __shared__ __align__(16) float s_agg[DE][KS_PAD];
    __shared__ float simired[256];
    __shared__ float simiS[DE][HEADS];
    __shared__ float smS[DE][HEADS];

    if (t < EN) sidx[t] = edges[((size_t)b * NN * EN + (size_t)n * EN + t) * 2];
    __syncthreads();

    // gather neighbor features (vectorized: 16 rows x 64 float4)
#pragma unroll
    for (int r = 0; r < 4; r++) {
        int i = r * 256 + t;
        int e = i >> 6, c4 = (i & 63) * 4;
        *(float4*)&sf[e][c4] =
            *(const float4*)&xin[((size_t)(b * NN + sidx[e])) * CC + c4];
    }
    // gather coords
    if (t < EN * 3) {
        int e = t / 3, d = t % 3;
        scs[e][d] = xyz[((size_t)(b * NN + sidx[e])) * 3 + d];
    }
    // gather precomputed edge-MLP logits: lg[de][e] = L[src, de]
    if (t < 128) {
        int e = t >> 3, de = t & 7;
        lg[de][e] = Lg[((size_t)(b * NN + sidx[e])) * DE + de];
    }
    // load rs (float4, coalesced): 8*272/4 = 544 vec4
    {
        const float4* Rv = (const float4*)(R + (size_t)m * DE * KS_PAD);
        float4* rsv = (float4*)&rs[0][0];
#pragma unroll
        for (int r = 0; r < 3; r++) {
            int i = r * 256 + t;
            if (i < DE * KS_PAD / 4) rsv[i] = Rv[i];
        }
    }
    __syncthreads();

    // gumbel softmax over EN per de row (tau = 0.1)
    if (t < DE) {
        float z[EN];
        float mx = -1e30f;
#pragma unroll
        for (int ee = 0; ee < EN; ee++) {
            float u = gu[(size_t)m * (DE * EN) + t * EN + ee];
            float gn = -logf(-logf(u));
            float zz = (lg[t][ee] + gn) * 10.0f;
            z[ee] = zz;
            mx = fmaxf(mx, zz);
        }
        float sum = 0.f;
#pragma unroll
        for (int ee = 0; ee < EN; ee++) {
            float ez = expf(z[ee] - mx);
            z[ee] = ez;
            sum += ez;
        }
        float inv = 1.0f / sum;
#pragma unroll
        for (int ee = 0; ee < EN; ee++) wsh[t][ee] = z[ee] * inv;
    }
    __syncthreads();

    // s_agg[d][c] = sum_e w[d][e]*sf[e][c]; cols 256..258 coords; 259.. = 0
    {
        int c = t; // 0..255
        float sfc[EN];
#pragma unroll
        for (int ee = 0; ee < EN; ee++) sfc[ee] = sf[ee][c];
#pragma unroll
        for (int d = 0; d < DE; d++) {
            float a = 0.f;
#pragma unroll
            for (int ee = 0; ee < EN; ee++) a = fmaf(wsh[d][ee], sfc[ee], a);
            s_agg[d][c] = a;
        }
        if (t < 16) {
            int c2 = 256 + t;
            if (c2 < C3) {
                int dim = t; // 0..2
                float ctr = xyz[((size_t)(b * NN + n)) * 3 + dim];
#pragma unroll
                for (int d = 0; d < DE; d++) {
                    float a = 0.f;
#pragma unroll
                    for (int ee = 0; ee < EN; ee++)
                        a = fmaf(wsh[d][ee], scs[ee][dim], a);
                    s_agg[d][c2] = a - ctr;
                }
            } else {
#pragma unroll
                for (int d = 0; d < DE; d++) s_agg[d][c2] = 0.f;
            }
        }
    }
    __syncthreads();

    // simi[d][h] = (s_agg[d] . rs[h]) / sqrt(32); 64 pairs x 4 partials
    {
        int dh = t >> 2, part = t & 3;
        int d = dh >> 3, hh = dh & 7;
        float p = 0.f;
        int cbeg = part * 68;
#pragma unroll 4
        for (int c = cbeg; c < cbeg + 68; c++)
            p = fmaf(s_agg[d][c], rs[hh][c], p);
        simired[t] = p;
    }
    __syncthreads();
    if (t < 64) {
        int d = t >> 3, hh = t & 7;
        float s = simired[t * 4] + simired[t * 4 + 1] +
                  simired[t * 4 + 2] + simired[t * 4 + 3];
        simiS[d][hh] = s * 0.17677669529663687f; // 1/sqrt(32)
    }
    __syncthreads();
    if (t < HEADS) {
        float mx = -1e30f;
#pragma unroll
        for (int d = 0; d < DE; d++) mx = fmaxf(mx, simiS[d][t]);
        float sum = 0.f;
#pragma unroll
        for (int d = 0; d < DE; d++) {
            float ez = expf(simiS[d][t] - mx);
            smS[d][t] = ez;
            sum += ez;
        }
        float inv = 1.0f / sum;
#pragma unroll
        for (int d = 0; d < DE; d++) smS[d][t] *= inv;
    }
    __syncthreads();

    // aggP[h][m][c] = sum_d smS[d][h] * s_agg[d][c]  (pads are zero)
    {
        int c = t;
        float sc[DE];
#pragma unroll
        for (int d = 0; d < DE; d++) sc[d] = s_agg[d][c];
#pragma unroll
        for (int hh = 0; hh < HEADS; hh++) {
            float a = 0.f;
#pragma unroll
            for (int d = 0; d < DE; d++) a = fmaf(smS[d][hh], sc[d], a);
            aggP[((size_t)hh * BN_TOT + m) * KS_PAD + c] = a;
        }
        if (t < 16) {
            int c2 = 256 + t;
            float sc2[DE];
#pragma unroll
            for (int d = 0; d < DE; d++) sc2[d] = s_agg[d][c2];
#pragma unroll
            for (int hh = 0; hh < HEADS; hh++) {
                float a = 0.f;
#pragma unroll
                for (int d = 0; d < DE; d++) a = fmaf(smS[d][hh], sc2[d], a);
                aggP[((size_t)hh * BN_TOT + m) * KS_PAD + c2] = a;
            }
        }
    }
}

// ---------------------------------------------------------------------------
// Per-head o GEMM: ao[n, h*32+j] = Agg_h[n, :] @ Wv[:, h*32+j]
// Tile 128x32, K=272 (Agg pads zero; Wv rows >= 259 read as zero).
// grid: (BN/128, HEADS), block: 256, microtile 4x4.
// ---------------------------------------------------------------------------
__global__ __launch_bounds__(256) void sgemm_h32(
    const float* __restrict__ Aall, const float* __restrict__ Wv,
    float* __restrict__ Cout) {
    int h = blockIdx.y;
    int m0 = blockIdx.x * 128;
    const float* A = Aall + (size_t)h * BN_TOT * KS_PAD;
    __shared__ __align__(16) float As[16][128];
    __shared__ __align__(16) float Bs[16][32];
    int t = threadIdx.x;
    int a_r = t >> 1, a_k8 = (t & 1) * 8;
    int ty = (t >> 3) * 4, tx = (t & 7) * 4;

    float acc[4][4];
#pragma unroll
    for (int u = 0; u < 4; u++)
#pragma unroll
        for (int v = 0; v < 4; v++) acc[u][v] = 0.f;

    const float* Arow = A + (size_t)(m0 + a_r) * KS_PAD + a_k8;

    for (int k0 = 0; k0 < KS_PAD; k0 += 16) {
        float4 a0 = *(const float4*)(Arow + k0);
        float4 a1 = *(const float4*)(Arow + k0 + 4);
        As[a_k8 + 0][a_r] = a0.x; As[a_k8 + 1][a_r] = a0.y;
        As[a_k8 + 2][a_r] = a0.z; As[a_k8 + 3][a_r] = a0.w;
        As[a_k8 + 4][a_r] = a1.x; As[a_k8 + 5][a_r] = a1.y;
        As[a_k8 + 6][a_r] = a1.z; As[a_k8 + 7][a_r] = a1.w;
        if (t < 128) {
            int bk = t >> 3, j4 = (t & 7) * 4;
            float4 bv = make_float4(0.f, 0.f, 0.f, 0.f);
            if (k0 + bk < C3)
                bv = *(const float4*)(Wv + (size_t)(k0 + bk) * CC + h * DD + j4);
            *(float4*)&Bs[bk][j4] = bv;
        }
        __syncthreads();
#pragma unroll
        for (int kk = 0; kk < 16; kk++) {
            float4 av = *(const float4*)&As[kk][ty];
            float4 bv = *(const float4*)&Bs[kk][tx];
            float aa[4] = {av.x, av.y, av.z, av.w};
            float bb[4] = {bv.x, bv.y, bv.z, bv.w};
#pragma unroll
            for (int u = 0; u < 4; u++)
#pragma unroll
                for (int v = 0; v < 4; v++)
                    acc[u][v] = fmaf(aa[u], bb[v], acc[u][v]);
        }
        __syncthreads();
    }
#pragma unroll
    for (int u = 0; u < 4; u++) {
        *(float4*)(Cout + (size_t)(m0 + ty + u) * CC + h * DD + tx) =
            make_float4(acc[u][0], acc[u][1], acc[u][2], acc[u][3]);
    }
}

// ---------------------------------------------------------------------------
// SGEMM: C(MxN) = A(MxK) @ B(KxN) [+ bias] [relu] [+ add]
// Tiles 128x128x16, 256 threads, 8x8 microtile via packed fma.rn.f32x2.
// Double-buffered SMEM, one __syncthreads per k-tile. grid: (N/128, M/128)
// ---------------------------------------------------------------------------
__global__ __launch_bounds__(256) void sgemm_kernel(
    const float* __restrict__ A, int lda,
    const float* __restrict__ B, int ldb,
    float* __restrict__ C, int ldc,
    int Kt, int Kreal,
    const float* __restrict__ bias,
    const float* __restrict__ add, int do_relu) {
    __shared__ __align__(16) float As[2][16][128];
    __shared__ __align__(16) float Bs[2][16][128];
    int t = threadIdx.x;
    int bm0 = blockIdx.y * 128;
    int bn0 = blockIdx.x * 128;

    int a_r = t >> 1;
    int a_k8 = (t & 1) * 8;
    int b_k = t >> 4;
    int b_c8 = (t & 15) * 8;
    int ty = (t >> 4) * 8;
    int tx = (t & 15) * 8;

    u64 acc2[8][4];
#pragma unroll
    for (int u = 0; u < 8; u++)
#pragma unroll
        for (int v = 0; v < 4; v++) acc2[u][v] = 0ull;

    const float* Arow = A + (size_t)(bm0 + a_r) * lda + a_k8;
    const float* Bbase = B + (size_t)b_k * ldb + bn0 + b_c8;

    int ntile = Kt >> 4;

    {
        float4 a0 = *(const float4*)(Arow + 0);
        float4 a1 = *(const float4*)(Arow + 4);
        float4 bv0 = make_float4(0.f, 0.f, 0.f, 0.f);
        float4 bv1 = bv0;
        if (b_k < Kreal) {
            bv0 = *(const float4*)(Bbase + 0);
            bv1 = *(const float4*)(Bbase + 4);
        }
        As[0][a_k8 + 0][a_r] = a0.x; As[0][a_k8 + 1][a_r] = a0.y;
        As[0][a_k8 + 2][a_r] = a0.z; As[0][a_k8 + 3][a_r] = a0.w;
        As[0][a_k8 + 4][a_r] = a1.x; As[0][a_k8 + 5][a_r] = a1.y;
        As[0][a_k8 + 6][a_r] = a1.z; As[0][a_k8 + 7][a_r] = a1.w;
        *(float4*)&Bs[0][b_k][b_c8] = bv0;
        *(float4*)&Bs[0][b_k][b_c8 + 4] = bv1;
    }
    __syncthreads();

    for (int i = 0; i < ntile; i++) {
        int cur = i & 1;
        int nxt = cur ^ 1;
        float4 a0, a1, bv0, bv1;
        bool have_next = (i + 1) < ntile;
        if (have_next) {
            int k0 = (i + 1) << 4;
            a0 = *(const float4*)(Arow + k0);
            a1 = *(const float4*)(Arow + k0 + 4);
            bv0 = make_float4(0.f, 0.f, 0.f, 0.f);
            bv1 = bv0;
            if (k0 + b_k < Kreal) {
                bv0 = *(const float4*)(Bbase + (size_t)k0 * ldb);
                bv1 = *(const float4*)(Bbase + (size_t)k0 * ldb + 4);
            }
        }
#pragma unroll
        for (int kk = 0; kk < 16; kk++) {
            float4 x0 = *(const float4*)&As[cur][kk][ty];
            float4 x1 = *(const float4*)&As[cur][kk][ty + 4];
            ulonglong2 yA = *(const ulonglong2*)&Bs[cur][kk][tx];
            ulonglong2 yB = *(const ulonglong2*)&Bs[cur][kk][tx + 4];
            u64 bw2[4] = {yA.x, yA.y, yB.x, yB.y};
            float av[8] = {x0.x, x0.y, x0.z, x0.w, x1.x, x1.y, x1.z, x1.w};
#pragma unroll
            for (int u = 0; u < 8; u++) {
                u64 a2 = pack_dup(av[u]);
#pragma unroll
                for (int v = 0; v < 4; v++) ffma2(acc2[u][v], a2, bw2[v]);
            }
        }
        if (have_next) {
            As[nxt][a_k8 + 0][a_r] = a0.x; As[nxt][a_k8 + 1][a_r] = a0.y;
            As[nxt][a_k8 + 2][a_r] = a0.z; As[nxt][a_k8 + 3][a_r] = a0.w;
            As[nxt][a_k8 + 4][a_r] = a1.x; As[nxt][a_k8 + 5][a_r] = a1.y;
            As[nxt][a_k8 + 6][a_r] = a1.z; As[nxt][a_k8 + 7][a_r] = a1.w;
            *(float4*)&Bs[nxt][b_k][b_c8] = bv0;
            *(float4*)&Bs[nxt][b_k][b_c8 + 4] = bv1;
            __syncthreads();
        }
    }

#pragma unroll
    for (int u = 0; u < 8; u++) {
        int row = bm0 + ty + u;
        float o[8];
#pragma unroll
        for (int v = 0; v < 4; v++) {
            float2 p = unpack2(acc2[u][v]);
            o[v * 2] = p.x;
            o[v * 2 + 1] = p.y;
        }
#pragma unroll
        for (int v = 0; v < 8; v++) {
            float val = o[v];
            if (bias) val += bias[bn0 + tx + v];
            if (do_relu) val = val > 0.f ? val : 0.f;
            if (add) val += add[(size_t)row * ldc + bn0 + tx + v];
            o[v] = val;
        }
        *(float4*)(C + (size_t)row * ldc + bn0 + tx) =
            make_float4(o[0], o[1], o[2], o[3]);
        *(float4*)(C + (size_t)row * ldc + bn0 + tx + 4) =
            make_float4(o[4], o[5], o[6], o[7]);
    }
}

// ---------------------------------------------------------------------------
// Launcher
// ---------------------------------------------------------------------------
extern "C" void kernel_launch(void* const* d_in, const int* in_sizes, int n_in,
                              void* d_out, int out_size) {
    const float* xyz = (const float*)d_in[0];
    const float* features = (const float*)d_in[1];
    const int* edges = (const int*)d_in[2];
    const float* gu = (const float*)d_in[3];
    const float* g1 = (const float*)d_in[4];
    const float* be1 = (const float*)d_in[5];
    const float* Wq = (const float*)d_in[6];
    const float* Wk = (const float*)d_in[7];
    const float* Wv = (const float*)d_in[8];
    const float* Wo = (const float*)d_in[9];
    const float* g2 = (const float*)d_in[10];
    const float* be2 = (const float*)d_in[11];
    const float* W1 = (const float*)d_in[12];
    const float* bf1 = (const float*)d_in[13];
    const float* W2 = (const float*)d_in[14];
    const float* bf2 = (const float*)d_in[15];
    const float* D1 = (const float*)d_in[16];
    const float* db1 = (const float*)d_in[17];
    const float* D2 = (const float*)d_in[18];
    const float* db2 = (const float*)d_in[19];
    float* out = (float*)d_out;

    float *featsT, *x, *qb, *Hb, *Lb, *rb, *agg, *ao, *f1, *mid, *f2;
    cudaGetSymbolAddress((void**)&featsT, g_featsT);
    cudaGetSymbolAddress((void**)&x, g_x);
    cudaGetSymbolAddress((void**)&qb, g_q);
    cudaGetSymbolAddress((void**)&Hb, g_H);
    cudaGetSymbolAddress((void**)&Lb, g_L);
    cudaGetSymbolAddress((void**)&rb, g_r);
    cudaGetSymbolAddress((void**)&agg, g_agg);
    cudaGetSymbolAddress((void**)&ao, g_ao);
    cudaGetSymbolAddress((void**)&f1, g_f1);
    cudaGetSymbolAddress((void**)&mid, g_mid);
    cudaGetSymbolAddress((void**)&f2, g_f2);

    // 1) features (B,C,N) -> featsT (B,N,C)
    transpose_kernel<<<dim3(NN / 32, CC / 32, BB), dim3(32, 8)>>>(features, featsT, CC, NN);
    // 2) x = LN1(featsT)
    ln_kernel<<<BN_TOT, 256>>>(featsT, x, g1, be1);
    // 3) H = relu(x @ D1 + db1)   (BN x 256 @ 256 x 128)
    sgemm_kernel<<<dim3(1, BN_TOT / 128), 256>>>(x, CC, D1, 128, Hb, 128,
                                                 CC, CC, db1, nullptr, 1);
    // 4) L = H @ D2 + db2         (BN x 128 @ 128 x 8)
    lproj_kernel<<<BN_TOT / 32, 256>>>(Hb, D2, db2, Lb);
    // 5) Q = x @ Wq
    sgemm_kernel<<<dim3(CC / 128, BN_TOT / 128), 256>>>(x, CC, Wq, CC, qb, CC,
                                                        CC, CC, nullptr, nullptr, 0);
    // 6) R[n,h,c] = Wk_h @ q_h
    rproj_kernel<<<dim3(KS_PAD / 16, BN_TOT / 16), 256>>>(qb, Wk, rb);
    // 7) node: gather + edge-select + s + attention weights + head aggregation
    node_kernel<<<BN_TOT, 256>>>(xyz, edges, gu, Lb, x, rb, agg);
    // 8) ao[:, h-block] = Agg_h @ Wv_h
    sgemm_h32<<<dim3(BN_TOT / 128, HEADS), 256>>>(agg, Wv, ao);
    // 9) f1 = featsT + ao @ Wo
    sgemm_kernel<<<dim3(CC / 128, BN_TOT / 128), 256>>>(ao, CC, Wo, CC, f1, CC,
                                                        CC, CC, nullptr, featsT, 0);
    // 10) x = LN2(f1)
    ln_kernel<<<BN_TOT, 256>>>(f1, x, g2, be2);
    // 11) mid = relu(x @ W1 + bf1)
    sgemm_kernel<<<dim3(FF / 128, BN_TOT / 128), 256>>>(x, CC, W1, FF, mid, FF,
                                                        CC, CC, bf1, nullptr, 1);
    // 12) f2 = f1 + mid @ W2 + bf2
    sgemm_kernel<<<dim3(CC / 128, BN_TOT / 128), 256>>>(mid, FF, W2, CC, f2, CC,
                                                        FF, FF, bf2, f1, 0);
    // 13) f2 (B,N,C) -> out (B,C,N)
    transpose_kernel<<<dim3(CC / 32, NN / 32, BB), dim3(32, 8)>>>(f2, out, NN, CC);
}